// round 3
// baseline (speedup 1.0000x reference)
#include <cuda_runtime.h>
#include <math.h>

#define Bz   32
#define Lz   256
#define DN   512
#define DE   64
#define NHh  32
#define FNh  1024
#define NTOK (Bz*Lz)
#define EPSF 1e-5f

typedef unsigned long long u64t;

__device__ __forceinline__ u64t pk2(float lo, float hi){
    u64t r; asm("mov.b64 %0,{%1,%2};" : "=l"(r) : "f"(lo), "f"(hi)); return r;
}
__device__ __forceinline__ void up2(u64t v, float& a, float& b){
    asm("mov.b64 {%0,%1},%2;" : "=f"(a), "=f"(b) : "l"(v));
}
__device__ __forceinline__ u64t fma2(u64t a, u64t b, u64t c){
    u64t d; asm("fma.rn.f32x2 %0,%1,%2,%3;" : "=l"(d) : "l"(a), "l"(b), "l"(c)); return d;
}
__device__ __forceinline__ float eluf(float x){
    return x > 0.f ? x : (__expf(x) - 1.f);
}

// ------------------------- scratch (device globals) -------------------------
__device__ __align__(16) float g_hln [NTOK*DN];
__device__ __align__(16) float g_qkv [(size_t)NTOK*3*DN];
__device__ __align__(16) float g_vatt[NTOK*DN];
__device__ __align__(16) float g_h2  [NTOK*DN];
__device__ __align__(16) float g_hff [NTOK*DN];
__device__ __align__(16) float g_t1  [(size_t)NTOK*FNh];

// ------------------------- LN over 512 (one row per block) ------------------
__global__ __launch_bounds__(256) void ln512_kernel(
    const float* __restrict__ x, const float* __restrict__ g,
    const float* __restrict__ bta, float* __restrict__ y)
{
    __shared__ float r1[8], r2[8];
    int row = blockIdx.x, t = threadIdx.x;
    const float* xr = x + (size_t)row * DN;
    float2 v = *(const float2*)(xr + 2*t);
    float s = v.x + v.y;
    #pragma unroll
    for (int o = 16; o; o >>= 1) s += __shfl_xor_sync(0xffffffffu, s, o);
    if ((t & 31) == 0) r1[t >> 5] = s;
    __syncthreads();
    float tot = 0.f;
    #pragma unroll
    for (int i = 0; i < 8; i++) tot += r1[i];
    float mean = tot * (1.f/512.f);
    float d0 = v.x - mean, d1 = v.y - mean;
    float q = d0*d0 + d1*d1;
    #pragma unroll
    for (int o = 16; o; o >>= 1) q += __shfl_xor_sync(0xffffffffu, q, o);
    if ((t & 31) == 0) r2[t >> 5] = q;
    __syncthreads();
    float tv = 0.f;
    #pragma unroll
    for (int i = 0; i < 8; i++) tv += r2[i];
    float rstd = rsqrtf(tv * (1.f/512.f) + EPSF);
    float2 gg = *(const float2*)(g   + 2*t);
    float2 bb = *(const float2*)(bta + 2*t);
    float2 o;
    o.x = d0 * rstd * gg.x + bb.x;
    o.y = d1 * rstd * gg.y + bb.y;
    *(float2*)(y + (size_t)row * DN + 2*t) = o;
}

// ------------------------- tiled fp32 GEMM (128x128x16) ---------------------
// C = act(A[M,K] @ W[K,N] + bias) (+ resid).  act: 0 none, 1 elu.
__global__ __launch_bounds__(256) void gemm_kernel(
    const float* __restrict__ A, const float* __restrict__ W,
    const float* __restrict__ bias, const float* __restrict__ resid,
    float* __restrict__ C, int N, int K, int act)
{
    __shared__ __align__(16) float As[16*132];
    __shared__ __align__(16) float Bs[16*132];
    int bm = blockIdx.y, bn = blockIdx.x;
    int t = threadIdx.x;
    int tx = t & 15, ty = t >> 4;
    int row0 = ty * 8, col0 = tx * 8;
    const float* Ab = A + (size_t)bm * 128 * K;
    const float* Wb = W + (size_t)bn * 128;

    u64t acc[8][4];
    #pragma unroll
    for (int i = 0; i < 8; i++)
        #pragma unroll
        for (int j = 0; j < 4; j++) acc[i][j] = 0ull;

    for (int k0 = 0; k0 < K; k0 += 16) {
        #pragma unroll
        for (int r = 0; r < 2; r++) {
            int id = t + 256*r, arow = id >> 2, ac4 = id & 3;
            float4 v = *(const float4*)(Ab + (size_t)arow * K + k0 + ac4*4);
            As[(ac4*4+0)*132 + arow] = v.x;
            As[(ac4*4+1)*132 + arow] = v.y;
            As[(ac4*4+2)*132 + arow] = v.z;
            As[(ac4*4+3)*132 + arow] = v.w;
        }
        #pragma unroll
        for (int r = 0; r < 2; r++) {
            int id = t + 256*r, brow = id >> 5, bc4 = id & 31;
            float4 v = *(const float4*)(Wb + (size_t)(k0 + brow) * N + bc4*4);
            *(float4*)&Bs[brow*132 + bc4*4] = v;
        }
        __syncthreads();
        #pragma unroll
        for (int kk = 0; kk < 16; kk++) {
            float a[8];
            #pragma unroll
            for (int i = 0; i < 2; i++) {
                float4 v = *(const float4*)&As[kk*132 + row0 + 4*i];
                a[4*i] = v.x; a[4*i+1] = v.y; a[4*i+2] = v.z; a[4*i+3] = v.w;
            }
            u64t b2[4];
            {
                ulonglong2 q0 = *(const ulonglong2*)&Bs[kk*132 + col0];
                ulonglong2 q1 = *(const ulonglong2*)&Bs[kk*132 + col0 + 4];
                b2[0] = q0.x; b2[1] = q0.y; b2[2] = q1.x; b2[3] = q1.y;
            }
            #pragma unroll
            for (int i = 0; i < 8; i++) {
                u64t as = pk2(a[i], a[i]);
                #pragma unroll
                for (int j = 0; j < 4; j++) acc[i][j] = fma2(as, b2[j], acc[i][j]);
            }
        }
        __syncthreads();
    }

    float bcol[8];
    #pragma unroll
    for (int j = 0; j < 8; j++) bcol[j] = bias[bn*128 + col0 + j];

    #pragma unroll
    for (int i = 0; i < 8; i++) {
        size_t crow = (size_t)(bm*128 + row0 + i) * N + bn*128 + col0;
        #pragma unroll
        for (int j = 0; j < 4; j++) {
            float x0, x1; up2(acc[i][j], x0, x1);
            x0 += bcol[2*j]; x1 += bcol[2*j+1];
            if (act) { x0 = eluf(x0); x1 = eluf(x1); }
            if (resid) { x0 += resid[crow + 2*j]; x1 += resid[crow + 2*j + 1]; }
            float2 o; o.x = x0; o.y = x1;
            *(float2*)(C + crow + 2*j) = o;
        }
    }
}

// ------------------------- fused e-path mega-kernel --------------------------
#define SMEM_FLOATS 40832
__global__ __launch_bounds__(256, 1) void egt_e_kernel(
    const float* __restrict__ e, const float* __restrict__ maskp,
    const float* __restrict__ qkv,
    const float* __restrict__ lneg, const float* __restrict__ lneb,
    const float* __restrict__ WE,  const float* __restrict__ bE,
    const float* __restrict__ WG,  const float* __restrict__ bG,
    const float* __restrict__ WOe, const float* __restrict__ bOe,
    const float* __restrict__ ffg, const float* __restrict__ ffb,
    const float* __restrict__ W1,  const float* __restrict__ b1,
    const float* __restrict__ W2,  const float* __restrict__ b2v,
    float* __restrict__ vatt, float* __restrict__ e_out)
{
    extern __shared__ __align__(16) float sm[];
    float* sq    = sm;            // 512
    float* sHs   = sq    + 512;   // 256*33
    float* sGs   = sHs   + 8448;  // 256*33
    float* sMask = sGs   + 8448;  // 256
    float* sRmax = sMask + 256;   // 32
    float* sRinv = sRmax + 32;    // 32
    float* sWE   = sRinv + 32;    // 2048
    float* sWG   = sWE   + 2048;  // 2048
    float* sWOe  = sWG   + 2048;  // 2048
    float* sW1t  = sWOe  + 2048;  // 8192
    float* sW2   = sW1t  + 8192;  // 8192
    float* sbE   = sW2   + 8192;  // 32
    float* sbG   = sbE   + 32;    // 32
    float* sbOe  = sbG   + 32;    // 64
    float* sb1   = sbOe  + 64;    // 128
    float* sb2   = sb1   + 128;   // 64
    float* sLg   = sb2   + 64;    // 64
    float* sLb   = sLg   + 64;    // 64
    float* sFg   = sLb   + 64;    // 64
    float* sFb   = sFg   + 64;    // 64

    const int tid  = threadIdx.x;
    const int b    = blockIdx.x / Lz;
    const int l    = blockIdx.x % Lz;
    const size_t tok = (size_t)b * Lz + l;

    for (int i = tid; i < 512; i += 256) sq[i] = qkv[tok*1536 + i];
    sMask[tid] = maskp[tok*Lz + tid];
    for (int i = tid; i < 2048; i += 256) { sWE[i] = WE[i]; sWG[i] = WG[i]; sWOe[i] = WOe[i]; }
    for (int i = tid; i < 8192; i += 256) {
        int j = i >> 7, k = i & 127;
        sW1t[k*64 + j] = W1[i];
        sW2[i] = W2[i];
    }
    if (tid < 32)  { sbE[tid] = bE[tid]; sbG[tid] = bG[tid]; }
    if (tid < 64)  { sbOe[tid] = bOe[tid]; sb2[tid] = b2v[tid];
                     sLg[tid] = lneg[tid]; sLb[tid] = lneb[tid];
                     sFg[tid] = ffg[tid];  sFb[tid] = ffb[tid]; }
    if (tid < 128) sb1[tid] = b1[tid];
    __syncthreads();

    // ---- phase 1: per-m e-LN, E/G projections, A_hat ----
    {
        const int m = tid;
        const float* erow = e + (tok*Lz + m) * DE;
        float ev[64]; float s0 = 0.f;
        #pragma unroll
        for (int i = 0; i < 16; i++) {
            float4 v = *(const float4*)(erow + 4*i);
            ev[4*i] = v.x; ev[4*i+1] = v.y; ev[4*i+2] = v.z; ev[4*i+3] = v.w;
            s0 += (v.x + v.y) + (v.z + v.w);
        }
        float mean = s0 * (1.f/64.f);
        float vs = 0.f;
        #pragma unroll
        for (int j = 0; j < 64; j++) { float d = ev[j] - mean; vs += d*d; }
        float rstd = rsqrtf(vs * (1.f/64.f) + EPSF);
        #pragma unroll
        for (int j = 0; j < 64; j++) ev[j] = (ev[j] - mean) * rstd * sLg[j] + sLb[j];

        u64t aE[16], aG[16];
        #pragma unroll
        for (int i = 0; i < 16; i++) {
            aE[i] = pk2(sbE[2*i], sbE[2*i+1]);
            aG[i] = pk2(sbG[2*i], sbG[2*i+1]);
        }
        #pragma unroll 8
        for (int j = 0; j < 64; j++) {
            u64t x = pk2(ev[j], ev[j]);
            const ulonglong2* we = (const ulonglong2*)(sWE + j*32);
            const ulonglong2* wg = (const ulonglong2*)(sWG + j*32);
            #pragma unroll
            for (int i4 = 0; i4 < 8; i4++) {
                ulonglong2 wa = we[i4];
                aE[2*i4]   = fma2(x, wa.x, aE[2*i4]);
                aE[2*i4+1] = fma2(x, wa.y, aE[2*i4+1]);
                ulonglong2 wb = wg[i4];
                aG[2*i4]   = fma2(x, wb.x, aG[2*i4]);
                aG[2*i4+1] = fma2(x, wb.y, aG[2*i4+1]);
            }
        }
        const float* krow = qkv + ((size_t)b*Lz + m)*1536 + 512;
        u64t a2[16];
        #pragma unroll
        for (int i = 0; i < 16; i++) a2[i] = 0ull;
        #pragma unroll
        for (int d = 0; d < 16; d++) {
            const ulonglong2* kp = (const ulonglong2*)(krow + d*32);
            const ulonglong2* qp = (const ulonglong2*)(sq   + d*32);
            #pragma unroll
            for (int i4 = 0; i4 < 8; i4++) {
                ulonglong2 kv = kp[i4], qv = qp[i4];
                a2[2*i4]   = fma2(qv.x, kv.x, a2[2*i4]);
                a2[2*i4+1] = fma2(qv.y, kv.y, a2[2*i4+1]);
            }
        }
        #pragma unroll
        for (int i = 0; i < 16; i++) {
            float a0, a1, E0, E1, g0, g1;
            up2(a2[i], a0, a1); up2(aE[i], E0, E1); up2(aG[i], g0, g1);
            a0 = fminf(fmaxf(a0 * 0.25f, -5.f), 5.f) + E0;
            a1 = fminf(fmaxf(a1 * 0.25f, -5.f), 5.f) + E1;
            sHs[m*33 + 2*i]     = a0; sHs[m*33 + 2*i + 1] = a1;
            sGs[m*33 + 2*i]     = g0; sGs[m*33 + 2*i + 1] = g1;
        }
    }
    __syncthreads();

    // ---- phase 2: softmax stats per head ----
    {
        int warp = tid >> 5, lane = tid & 31;
        #pragma unroll
        for (int hh = 0; hh < 4; hh++) {
            int h = warp*4 + hh;
            float mx = -1e30f;
            for (int m = lane; m < 256; m += 32)
                mx = fmaxf(mx, sHs[m*33 + h] + sMask[m]);
            #pragma unroll
            for (int o = 16; o; o >>= 1) mx = fmaxf(mx, __shfl_xor_sync(0xffffffffu, mx, o));
            float ss = 0.f;
            for (int m = lane; m < 256; m += 32)
                ss += __expf(sHs[m*33 + h] + sMask[m] - mx);
            #pragma unroll
            for (int o = 16; o; o >>= 1) ss += __shfl_xor_sync(0xffffffffu, ss, o);
            if (lane == 0) { sRmax[h] = mx; sRinv[h] = 1.f / ss; }
        }
    }
    __syncthreads();

    // ---- phase 2b: A_tild = softmax * sigmoid(G+mask) (in place of Gs) ----
    {
        const int m = tid;
        float ms = sMask[m];
        #pragma unroll 4
        for (int h = 0; h < 32; h++) {
            float p = __expf(sHs[m*33 + h] + ms - sRmax[h]) * sRinv[h];
            float gv = sGs[m*33 + h] + ms;
            float gate = 1.f / (1.f + __expf(-gv));
            sGs[m*33 + h] = p * gate;
        }
    }
    __syncthreads();

    // ---- phase 3: V_att[k,h] = sum_m A_tild[m,h] * V[b,m,k,h] ----
    {
        const int h = tid & 31;
        const int k0 = (tid >> 5) * 2;
        const float* vp = qkv + (size_t)b*Lz*1536 + 1024 + k0*32 + h;
        float acc0 = 0.f, acc1 = 0.f;
        #pragma unroll 8
        for (int m = 0; m < 256; m++) {
            float g = sGs[m*33 + h];
            const float* p = vp + (size_t)m * 1536;
            acc0 += g * p[0];
            acc1 += g * p[32];
        }
        vatt[tok*DN + k0*32 + h]     = acc0;
        vatt[tok*DN + (k0+1)*32 + h] = acc1;
    }

    // ---- phase 4: e2 = Hs@W_Oe + bOe + e; LN; FFN 64->128->64; e_out ----
    {
        const int m = tid;
        u64t e2p[32];
        #pragma unroll
        for (int i = 0; i < 32; i++) e2p[i] = pk2(sbOe[2*i], sbOe[2*i+1]);
        #pragma unroll 4
        for (int h = 0; h < 32; h++) {
            float hv = sHs[m*33 + h];
            u64t x = pk2(hv, hv);
            const ulonglong2* w = (const ulonglong2*)(sWOe + h*64);
            #pragma unroll
            for (int i4 = 0; i4 < 16; i4++) {
                ulonglong2 ww = w[i4];
                e2p[2*i4]   = fma2(x, ww.x, e2p[2*i4]);
                e2p[2*i4+1] = fma2(x, ww.y, e2p[2*i4+1]);
            }
        }
        const float* erow = e + (tok*Lz + m) * DE;
        float e2vv[64]; float s0 = 0.f;
        #pragma unroll
        for (int i = 0; i < 32; i++) {
            float x0, x1; up2(e2p[i], x0, x1);
            float2 ee = *(const float2*)(erow + 2*i);
            x0 += ee.x; x1 += ee.y;
            e2vv[2*i] = x0; e2vv[2*i+1] = x1;
            s0 += x0 + x1;
        }
        float mean = s0 * (1.f/64.f);
        float vs = 0.f;
        #pragma unroll
        for (int j = 0; j < 64; j++) { float d = e2vv[j] - mean; vs += d*d; }
        float rstd = rsqrtf(vs * (1.f/64.f) + EPSF);

        u64t outp[32], effp[32];
        #pragma unroll
        for (int i = 0; i < 32; i++) {
            outp[i] = pk2(e2vv[2*i] + sb2[2*i], e2vv[2*i+1] + sb2[2*i+1]);
            float f0 = (e2vv[2*i]   - mean) * rstd * sFg[2*i]   + sFb[2*i];
            float f1 = (e2vv[2*i+1] - mean) * rstd * sFg[2*i+1] + sFb[2*i+1];
            effp[i] = pk2(f0, f1);
        }
        #pragma unroll 2
        for (int k = 0; k < 128; k++) {
            const ulonglong2* w1p = (const ulonglong2*)(sW1t + k*64);
            u64t sa = 0ull, sb = 0ull;
            #pragma unroll
            for (int i4 = 0; i4 < 16; i4++) {
                ulonglong2 ww = w1p[i4];
                sa = fma2(effp[2*i4],   ww.x, sa);
                sb = fma2(effp[2*i4+1], ww.y, sb);
            }
            float x0, x1, y0, y1; up2(sa, x0, x1); up2(sb, y0, y1);
            float sv = (x0 + x1) + (y0 + y1) + sb1[k];
            float fv = eluf(sv);
            u64t f2 = pk2(fv, fv);
            const ulonglong2* w2p = (const ulonglong2*)(sW2 + k*64);
            #pragma unroll
            for (int i4 = 0; i4 < 16; i4++) {
                ulonglong2 ww = w2p[i4];
                outp[2*i4]   = fma2(f2, ww.x, outp[2*i4]);
                outp[2*i4+1] = fma2(f2, ww.y, outp[2*i4+1]);
            }
        }
        float* eo = e_out + (tok*Lz + m) * DE;
        #pragma unroll
        for (int i = 0; i < 16; i++) {
            float a0, a1, c0, c1;
            up2(outp[2*i],   a0, a1);
            up2(outp[2*i+1], c0, c1);
            float4 v; v.x = a0; v.y = a1; v.z = c0; v.w = c1;
            *(float4*)(eo + 4*i) = v;
        }
    }
}

// ----------------------------- host launcher --------------------------------
extern "C" void kernel_launch(void* const* d_in, const int* in_sizes, int n_in,
                              void* d_out, int out_size)
{
    const float* h_in   = (const float*)d_in[0];
    const float* e_in   = (const float*)d_in[1];
    const float* mask   = (const float*)d_in[2];
    const float* ln_h_g = (const float*)d_in[3];
    const float* ln_h_b = (const float*)d_in[4];
    const float* ln_e_g = (const float*)d_in[5];
    const float* ln_e_b = (const float*)d_in[6];
    const float* ffn_ln_h_g = (const float*)d_in[7];
    const float* ffn_ln_h_b = (const float*)d_in[8];
    const float* ffn_ln_e_g = (const float*)d_in[9];
    const float* ffn_ln_e_b = (const float*)d_in[10];
    const float* W_qkv = (const float*)d_in[11];
    const float* b_qkv = (const float*)d_in[12];
    const float* W_E   = (const float*)d_in[13];
    const float* b_E   = (const float*)d_in[14];
    const float* W_G   = (const float*)d_in[15];
    const float* b_G   = (const float*)d_in[16];
    const float* W_Oh  = (const float*)d_in[17];
    const float* b_Oh  = (const float*)d_in[18];
    const float* W_h1  = (const float*)d_in[19];
    const float* b_h1  = (const float*)d_in[20];
    const float* W_h2  = (const float*)d_in[21];
    const float* b_h2  = (const float*)d_in[22];
    const float* W_Oe  = (const float*)d_in[23];
    const float* b_Oe  = (const float*)d_in[24];
    const float* W_e1  = (const float*)d_in[25];
    const float* b_e1  = (const float*)d_in[26];
    const float* W_e2  = (const float*)d_in[27];
    const float* b_e2  = (const float*)d_in[28];

    float* h_out = (float*)d_out;
    float* e_out = (float*)d_out + (size_t)NTOK * DN;

    float *hln, *qkv, *vatt, *h2b, *hff, *t1;
    cudaGetSymbolAddress((void**)&hln,  g_hln);
    cudaGetSymbolAddress((void**)&qkv,  g_qkv);
    cudaGetSymbolAddress((void**)&vatt, g_vatt);
    cudaGetSymbolAddress((void**)&h2b,  g_h2);
    cudaGetSymbolAddress((void**)&hff,  g_hff);
    cudaGetSymbolAddress((void**)&t1,   g_t1);

    const int smem_bytes = SMEM_FLOATS * 4;
    cudaFuncSetAttribute(egt_e_kernel, cudaFuncAttributeMaxDynamicSharedMemorySize, smem_bytes);

    // 1) h LayerNorm
    ln512_kernel<<<NTOK, 256>>>(h_in, ln_h_g, ln_h_b, hln);

    // 2) QKV = h_ln @ W_qkv + b_qkv   [8192,512]x[512,1536]
    {
        dim3 grid(1536/128, NTOK/128);
        gemm_kernel<<<grid, 256>>>(hln, W_qkv, b_qkv, nullptr, qkv, 1536, 512, 0);
    }

    // 3) fused e-path (also produces V_att)
    egt_e_kernel<<<NTOK, 256, smem_bytes>>>(
        e_in, mask, qkv,
        ln_e_g, ln_e_b, W_E, b_E, W_G, b_G,
        W_Oe, b_Oe, ffn_ln_e_g, ffn_ln_e_b,
        W_e1, b_e1, W_e2, b_e2,
        vatt, e_out);

    // 4) h2 = V_att @ W_Oh + b_Oh + h
    {
        dim3 grid(512/128, NTOK/128);
        gemm_kernel<<<grid, 256>>>(vatt, W_Oh, b_Oh, h_in, h2b, 512, 512, 0);
    }

    // 5) h FFN LayerNorm
    ln512_kernel<<<NTOK, 256>>>(h2b, ffn_ln_h_g, ffn_ln_h_b, hff);

    // 6) t1 = elu(h_ff @ W_h1 + b_h1)
    {
        dim3 grid(1024/128, NTOK/128);
        gemm_kernel<<<grid, 256>>>(hff, W_h1, b_h1, nullptr, t1, 1024, 512, 1);
    }

    // 7) h_out = t1 @ W_h2 + b_h2 + h2
    {
        dim3 grid(512/128, NTOK/128);
        gemm_kernel<<<grid, 256>>>(t1, W_h2, b_h2, h2b, h_out, 512, 1024, 0);
    }
}